// round 17
// baseline (speedup 1.0000x reference)
#include <cuda_runtime.h>
#include <cuda_bf16.h>
#include <cstdint>

#define HD 128
#define WPB 8                       // warps per CTA
#define NTHREADS (WPB * 32)
#define GRID1 740                   // 148 SMs * 5 CTAs = exactly resident capacity at regs<=48
#define NWTOT (GRID1 * WPB)         // 5920 worker warps
#define BMAX 2048                   // scratch sized for up to 2048 segments

// ---- persistent scratch (zero-initialized at module load) ----
// g_seg_end[s]: 0 = not yet written (this run), j>=1 = true end row, -1 = empty marker.
// g_seg_start[s]: start_row + 1 (0 = not yet written).
// Every value is rewritten identically on every replay (deterministic writers);
// g_done[s] is reset to 0 by s's reducer after use, so replays start clean.
__device__ float g_head_num[NWTOT * HD];
__device__ float g_tail_num[NWTOT * HD];
__device__ float g_head_d[NWTOT];
__device__ float g_tail_d[NWTOT];
__device__ int   g_head_seg[NWTOT];
__device__ int   g_tail_seg[NWTOT];
__device__ float g_num_acc[BMAX * HD];   // direct-stored exclusive segments
__device__ float g_d_acc[BMAX];
__device__ int   g_seg_start[BMAX];
__device__ int   g_seg_end[BMAX];
__device__ int   g_done[BMAX];           // per-segment producer arrival count

// Single fused kernel.
// Streaming phase (identical math to the 87.7us two-kernel best): warp g owns
// contiguous rows [g*rpw, min((g+1)*rpw,N)); per same-segment run accumulate
// d = sum exp(s_i), num = sum exp(s_i)*x_i; flush to exclusive slot or this
// warp's head/tail slot; then fence + arrive on g_done[seg].
// Reduction phase (replaces the old K2 launch): warp g<B reduces segment g as
// soon as ITS producers have arrived - point-to-point sync, no grid barrier.
// All 740 CTAs are co-resident (launch_bounds min 5 CTAs/SM, grid == capacity),
// so the spins are deadlock-free.
__global__ void __launch_bounds__(NTHREADS, 5)
gap_fused(const float* __restrict__ x,
          const int*   __restrict__ batch,
          const float* __restrict__ W,
          float*       __restrict__ out,
          int N, int B)
{
    const int wid  = threadIdx.x >> 5;
    const int lane = threadIdx.x & 31;
    const int g    = blockIdx.x * WPB + wid;

    const int rpw = (N + NWTOT - 1) / NWTOT;
    const long long rl = (long long)g * rpw;

    // ---------------- streaming phase ----------------
    if (rl < N) {
        const int lo = (int)rl;
        const int hi = min(lo + rpw, N);
        const float4 Wv = *reinterpret_cast<const float4*>(W + lane * 4);
        const long long col = (long long)lane * 4;

        // sentinel-init this warp's slot ids BEFORE any flush/arrive, so a
        // reducer that scans this slot (exclusive-segment case) can never see
        // a stale id from zero-init / a previous replay.
        if (lane == 0) { g_head_seg[g] = -1; g_tail_seg[g] = -1; }

        int i = lo;
        while (i < hi) {
            const int seg = batch[i];
            // upper_bound(seg) in (i, hi)
            int a = i + 1, b = hi;
            while (a < b) { int m = (a + b) >> 1; if (batch[m] <= seg) a = m + 1; else b = m; }
            const int j = a;

            float  d = 0.0f;
            float4 num = make_float4(0.0f, 0.0f, 0.0f, 0.0f);

            int r = i;
            // 4 consecutive rows per iter: 4 independent LDG.128, 2KB contiguous
            for (; r + 4 <= j; r += 4) {
                const float4 x0 = __ldcs(reinterpret_cast<const float4*>(x + (long long)(r    ) * HD + col));
                const float4 x1 = __ldcs(reinterpret_cast<const float4*>(x + (long long)(r + 1) * HD + col));
                const float4 x2 = __ldcs(reinterpret_cast<const float4*>(x + (long long)(r + 2) * HD + col));
                const float4 x3 = __ldcs(reinterpret_cast<const float4*>(x + (long long)(r + 3) * HD + col));

                float p0 = x0.x * Wv.x + x0.y * Wv.y + x0.z * Wv.z + x0.w * Wv.w;
                float p1 = x1.x * Wv.x + x1.y * Wv.y + x1.z * Wv.z + x1.w * Wv.w;
                float p2 = x2.x * Wv.x + x2.y * Wv.y + x2.z * Wv.z + x2.w * Wv.w;
                float p3 = x3.x * Wv.x + x3.y * Wv.y + x3.z * Wv.z + x3.w * Wv.w;
                #pragma unroll
                for (int o = 16; o > 0; o >>= 1) {
                    p0 += __shfl_xor_sync(0xffffffffu, p0, o);
                    p1 += __shfl_xor_sync(0xffffffffu, p1, o);
                    p2 += __shfl_xor_sync(0xffffffffu, p2, o);
                    p3 += __shfl_xor_sync(0xffffffffu, p3, o);
                }
                const float e0 = __expf(p0);
                const float e1 = __expf(p1);
                const float e2 = __expf(p2);
                const float e3 = __expf(p3);
                d += (e0 + e1) + (e2 + e3);
                num.x += e0 * x0.x + e1 * x1.x + e2 * x2.x + e3 * x3.x;
                num.y += e0 * x0.y + e1 * x1.y + e2 * x2.y + e3 * x3.y;
                num.z += e0 * x0.z + e1 * x1.z + e2 * x2.z + e3 * x3.z;
                num.w += e0 * x0.w + e1 * x1.w + e2 * x2.w + e3 * x3.w;
            }
            for (; r < j; r++) {
                const float4 xv = __ldcs(reinterpret_cast<const float4*>(x + (long long)r * HD + col));
                float p = xv.x * Wv.x + xv.y * Wv.y + xv.z * Wv.z + xv.w * Wv.w;
                #pragma unroll
                for (int o = 16; o > 0; o >>= 1) p += __shfl_xor_sync(0xffffffffu, p, o);
                const float e = __expf(p);
                d += e;
                num.x += e * xv.x; num.y += e * xv.y; num.z += e * xv.z; num.w += e * xv.w;
            }

            const bool sb = (i == lo) && (lo > 0) && (batch[lo - 1] == seg);   // continues before
            const bool ea = (j == hi) && (hi < N) && (batch[hi] == seg);       // continues after

            if (lane == 0) {
                if (!sb) {
                    // this warp owns the TRUE start of seg: record it and mark
                    // any empty segments in the gap before it.
                    const int p = (i > 0) ? batch[i - 1] : -1;
                    for (int s2 = p + 1; s2 < seg; s2++) g_seg_end[s2] = -1;
                    g_seg_start[seg] = i + 1;           // +1 encoding (0 = unwritten)
                }
                if (!ea) {
                    g_seg_end[seg] = j;                 // true end (j >= 1)
                    if (j == N) {                       // trailing empty segments
                        for (int s2 = seg + 1; s2 < B; s2++) g_seg_end[s2] = -1;
                    }
                }
            }

            if (!sb && !ea) {
                *reinterpret_cast<float4*>(g_num_acc + (long long)seg * HD + lane * 4) = num;
                if (lane == 0) g_d_acc[seg] = d;
            } else if (sb) {
                if (lane == 0) { g_head_seg[g] = seg; g_head_d[g] = d; }
                *reinterpret_cast<float4*>(g_head_num + (long long)g * HD + lane * 4) = num;
            } else {
                if (lane == 0) { g_tail_seg[g] = seg; g_tail_d[g] = d; }
                *reinterpret_cast<float4*>(g_tail_num + (long long)g * HD + lane * 4) = num;
            }

            // publish: everything above (bounds, slot ids, data) visible before arrive
            __threadfence();
            if (lane == 0) atomicAdd(&g_done[seg], 1);

            i = j;
        }
    }

    // ---------------- reduction phase: warp g reduces segment g ----------------
    if (g < B) {
        const int s = g;
        float4* outv = reinterpret_cast<float4*>(out + (long long)s * HD + lane * 4);

        int se = 0;
        if (lane == 0) {
            while ((se = *(volatile int*)&g_seg_end[s]) == 0) __nanosleep(64);
        }
        se = __shfl_sync(0xffffffffu, se, 0);

        if (se < 0) {
            // empty segment
            *outv = make_float4(0.0f, 0.0f, 0.0f, 0.0f);
        } else {
            int ssp = 0;
            if (lane == 0) {
                while ((ssp = *(volatile int*)&g_seg_start[s]) == 0) __nanosleep(64);
            }
            ssp = __shfl_sync(0xffffffffu, ssp, 0);
            const int ss  = ssp - 1;
            const int glo = ss / rpw;
            const int ghi = (se - 1) / rpw;
            const int expected = ghi - glo + 1;

            if (lane == 0) {
                while (*(volatile int*)&g_done[s] < expected) __nanosleep(64);
            }
            __syncwarp();
            __threadfence();   // acquire: producers' fenced stores now visible

            float4 num = make_float4(0.0f, 0.0f, 0.0f, 0.0f);
            float  d = 0.0f;
            int matches = 0;
            for (int gg = glo; gg <= ghi; gg++) {
                if (__ldcg(&g_head_seg[gg]) == s) {
                    const float4 v = __ldcg(reinterpret_cast<const float4*>(g_head_num + (long long)gg * HD + lane * 4));
                    num.x += v.x; num.y += v.y; num.z += v.z; num.w += v.w;
                    d += __ldcg(&g_head_d[gg]); matches++;
                }
                if (__ldcg(&g_tail_seg[gg]) == s) {
                    const float4 v = __ldcg(reinterpret_cast<const float4*>(g_tail_num + (long long)gg * HD + lane * 4));
                    num.x += v.x; num.y += v.y; num.z += v.z; num.w += v.w;
                    d += __ldcg(&g_tail_d[gg]); matches++;
                }
            }
            if (matches == 0) {
                num = __ldcg(reinterpret_cast<const float4*>(g_num_acc + (long long)s * HD + lane * 4));
                d   = __ldcg(&g_d_acc[s]);
            }
            const float inv = 1.0f / (d + 1e-16f);
            num.x *= inv; num.y *= inv; num.z *= inv; num.w *= inv;
            *outv = num;

            if (lane == 0) g_done[s] = 0;   // reset for the next replay
        }
    }
}

extern "C" void kernel_launch(void* const* d_in, const int* in_sizes, int n_in,
                              void* d_out, int out_size)
{
    const float* x     = (const float*)d_in[0];
    // d_in[1] = edge_index (unused by the forward math)
    const int*   batch = (const int*)d_in[2];
    const float* W     = (const float*)d_in[3];
    // d_in[4] = b (zeros; cancels in the softmax)
    float* out = (float*)d_out;

    const int N = in_sizes[2];
    const int B = out_size / HD;

    gap_fused<<<GRID1, NTHREADS>>>(x, batch, W, out, N, B);
}